// round 16
// baseline (speedup 1.0000x reference)
#include <cuda_runtime.h>

// Problem constants (fixed by reference setup_inputs)
#define BB   4
#define NN   10
#define KK   5
#define QTOT 512
#define DD   1536
#define D4   (DD / 4)        // 384 float4 per row

#define CH   64              // query row-chunks per batch
#define QC   (QTOT / CH)     // 8 rows per chunk
#define GRID (BB * CH)       // 256 blocks
#define TPB  384             // one thread per float4 column (12 warps)
#define NBN  (BB * NN)       // 40 phase-2 blocks
#define NZB  16              // cleanup blocks (16*384 = 6144 = BB*DD)

// Scratch. INVARIANT: g_qbar/g_qsq are ZERO at kernel entry (module-load zero
// init; each run re-zeroes them after use). Counters likewise self-reset.
__device__ float    g_qbar[BB * DD];   // sum over queries
__device__ float    g_qsq[BB];         // sum of squared query elems
__device__ unsigned g_bar;             // grid barrier
__device__ unsigned g_rdone;           // phase-2 reader completions
__device__ unsigned g_done;            // final counter reset

__global__ void __launch_bounds__(TPB, 2)
fused_kernel(const float* __restrict__ support,
             const float* __restrict__ query,
             float* __restrict__ out_agg,
             float* __restrict__ out_qgw)
{
    const int tid  = threadIdx.x;          // 0..383
    const int lane = tid & 31, warp = tid >> 5;
    const int bn   = blockIdx.x;
    const bool is_p2 = (bn < NBN);

    __shared__ float s_sup[KK * DD];       // 30720 B support tile
    __shared__ float sred[2 * KK][12];
    __shared__ float sw[KK];
    __shared__ float swsq[12];

    // ---- Phase 0: fire-and-forget support prefetch (phase-2 blocks) -------
    if (is_p2) {
        const float4* Sg = reinterpret_cast<const float4*>(support + (size_t)bn * KK * DD);
        unsigned saddr;
        asm("{ .reg .u64 t; cvta.to.shared.u64 t, %1; cvt.u32.u64 %0, t; }"
            : "=r"(saddr) : "l"(&s_sup[0]));
        #pragma unroll
        for (int i = 0; i < 5; i++) {                 // KK*D4 = 1920 = 5*384
            unsigned dst = saddr + (unsigned)(i * TPB + tid) * 16u;
            const float4* src = Sg + i * TPB + tid;
            asm volatile("cp.async.ca.shared.global [%0], [%1], 16;"
                         :: "r"(dst), "l"(src));
        }
        asm volatile("cp.async.commit_group;");
    }

    // ---- Phase 1: stream query chunk, atomic-accumulate qbar --------------
    {
        const int b = bn >> 6;               // bn / CH
        const int c = bn & 63;               // bn % CH
        const float4* qb = reinterpret_cast<const float4*>(query)
                         + (size_t)b * QTOT * D4 + (size_t)c * QC * D4 + tid;

        float4 acc = make_float4(0.f, 0.f, 0.f, 0.f);
        float sq = 0.0f;
        #pragma unroll
        for (int q = 0; q < QC; q++) {
            float4 v = qb[q * D4];           // 8 independent coalesced LDG.128
            acc.x += v.x; acc.y += v.y; acc.z += v.z; acc.w += v.w;
            sq += v.x*v.x + v.y*v.y + v.z*v.z + v.w*v.w;
        }

        float* dst = &g_qbar[b * DD + tid * 4];   // qbar is zero on entry
        atomicAdd(dst + 0, acc.x);
        atomicAdd(dst + 1, acc.y);
        atomicAdd(dst + 2, acc.z);
        atomicAdd(dst + 3, acc.w);

        #pragma unroll
        for (int off = 16; off > 0; off >>= 1)
            sq += __shfl_down_sync(0xFFFFFFFFu, sq, off);
        if (lane == 0) swsq[warp] = sq;
        __syncthreads();
        if (tid == 0) {
            float s = 0.f;
            #pragma unroll
            for (int w = 0; w < 12; w++) s += swsq[w];
            atomicAdd(&g_qsq[b], s);
        }
    }

    // ---- Single grid barrier (plain spin, no nanosleep) -------------------
    __threadfence();
    __syncthreads();
    if (tid == 0) {
        atomicAdd(&g_bar, 1u);
        while (*((volatile unsigned*)&g_bar) < GRID) { }
    }
    __syncthreads();
    __threadfence();

    // ---- Phase 2: per-(b,n) weights + aggregation (40 blocks) -------------
    if (is_p2) {
        asm volatile("cp.async.wait_group 0;");
        __syncthreads();                     // support tile resident in smem

        const int b = bn / NN;
        const float invQ = 1.0f / (float)QTOT;

        // qbar column for this thread (24 KB region, L2-hot after atomics)
        float4 qv = *reinterpret_cast<const float4*>(&g_qbar[b * DD + tid * 4]);

        float dot[KK], sn[KK];
        float4 sv[KK];
        #pragma unroll
        for (int k = 0; k < KK; k++) {
            sv[k] = *reinterpret_cast<const float4*>(&s_sup[k * DD + tid * 4]);
            dot[k] = sv[k].x*qv.x + sv[k].y*qv.y + sv[k].z*qv.z + sv[k].w*qv.w;
            sn[k]  = sv[k].x*sv[k].x + sv[k].y*sv[k].y + sv[k].z*sv[k].z + sv[k].w*sv[k].w;
        }

        #pragma unroll
        for (int k = 0; k < KK; k++) {
            float dv = dot[k], nv = sn[k];
            #pragma unroll
            for (int off = 16; off > 0; off >>= 1) {
                dv += __shfl_down_sync(0xFFFFFFFFu, dv, off);
                nv += __shfl_down_sync(0xFFFFFFFFu, nv, off);
            }
            if (lane == 0) { sred[k][warp] = dv; sred[KK + k][warp] = nv; }
        }
        __syncthreads();

        if (tid == 0) {
            float qn = g_qsq[b] * invQ;          // mean_q ||q||^2
            float t[KK], mx = -1e30f;
            #pragma unroll
            for (int k = 0; k < KK; k++) {
                float ds = 0.f, ns = 0.f;
                #pragma unroll
                for (int w = 0; w < 12; w++) { ds += sred[k][w]; ns += sred[KK + k][w]; }
                float m = -(ns - 2.0f * ds * invQ + qn);   // mean_q dist_sq
                t[k] = tanhf(m);
                mx = fmaxf(mx, t[k]);
            }
            float es = 0.f;
            #pragma unroll
            for (int k = 0; k < KK; k++) { t[k] = __expf(t[k] - mx); es += t[k]; }
            float inv = 1.0f / es;
            #pragma unroll
            for (int k = 0; k < KK; k++) {
                float wk = t[k] * inv;
                sw[k] = wk;
                out_qgw[bn * KK + k] = wk;
            }
        }
        __syncthreads();

        float w0 = sw[0], w1 = sw[1], w2 = sw[2], w3 = sw[3], w4 = sw[4];
        float4 a;
        a.x = sv[0].x*w0 + sv[1].x*w1 + sv[2].x*w2 + sv[3].x*w3 + sv[4].x*w4;
        a.y = sv[0].y*w0 + sv[1].y*w1 + sv[2].y*w2 + sv[3].y*w3 + sv[4].y*w4;
        a.z = sv[0].z*w0 + sv[1].z*w1 + sv[2].z*w2 + sv[3].z*w3 + sv[4].z*w4;
        a.w = sv[0].w*w0 + sv[1].w*w1 + sv[2].w*w2 + sv[3].w*w3 + sv[4].w*w4;
        reinterpret_cast<float4*>(out_agg + (size_t)bn * DD)[tid] = a;

        // Signal: this block is done reading g_qbar / g_qsq
        __threadfence();
        __syncthreads();
        if (tid == 0) atomicAdd(&g_rdone, 1u);
    }

    // ---- Cleanup: restore zero-state for next replay (blocks 0..15) -------
    if (bn < NZB) {
        if (tid == 0) {
            while (*((volatile unsigned*)&g_rdone) < NBN) { }
        }
        __syncthreads();
        g_qbar[bn * TPB + tid] = 0.0f;      // 16*384 = BB*DD
        if (bn == 0 && tid < BB) g_qsq[tid] = 0.0f;
        __threadfence();
    }

    // ---- Counter reset by the last block to finish -------------------------
    if (tid == 0) {
        __threadfence();
        unsigned old = atomicAdd(&g_done, 1u);
        if (old == GRID - 1) {
            atomicExch(&g_bar, 0u);
            atomicExch(&g_rdone, 0u);
            atomicExch(&g_done, 0u);
        }
    }
}

extern "C" void kernel_launch(void* const* d_in, const int* in_sizes, int n_in,
                              void* d_out, int out_size) {
    const float* support = (const float*)d_in[0];
    const float* query   = (const float*)d_in[1];
    float* out = (float*)d_out;

    float* out_agg = out;                          // (B,N,D)
    float* out_qgw = out + (size_t)BB * NN * DD;   // (B,N,K,1)

    fused_kernel<<<GRID, TPB>>>(support, query, out_agg, out_qgw);
}

// round 17
// speedup vs baseline: 1.2801x; 1.2801x over previous
#include <cuda_runtime.h>

// Problem constants (fixed by reference setup_inputs)
#define BB   4
#define NN   10
#define KK   5
#define QTOT 512
#define DD   1536
#define D4   (DD / 4)        // 384 float4 per row

#define CH   32              // query chunks per batch
#define QC   (QTOT / CH)     // 16 query rows per block
#define GRID (BB * CH)       // 128 blocks
#define TPB  128
#define NBN  (BB * NN)       // 40 consumer blocks

// Scratch (device globals; counters self-reset each run; partials are plain
// stores so no zero-state is required)
__device__ float    g_part[BB][CH][DD];  // per-chunk column sums of query
__device__ float    g_sq[BB][CH];        // per-chunk sum of squared elems
__device__ unsigned g_bar;               // grid barrier arrivals
__device__ unsigned g_done;              // completion counter (for reset)

__global__ void __launch_bounds__(TPB, 2)
fused_kernel(const float* __restrict__ support,
             const float* __restrict__ query,
             float* __restrict__ out_agg,
             float* __restrict__ out_qgw)
{
    const int tid  = threadIdx.x;          // 0..127
    const int lane = tid & 31, warp = tid >> 5;
    const int bn   = blockIdx.x;
    const bool is_p2 = (bn < NBN);

    __shared__ float s_sup[KK * DD];       // 30720 B support tile (consumers)
    __shared__ float sred[2 * KK][4];
    __shared__ float sw[KK];
    __shared__ float swsq[4];

    // ---- Phase 0: fire-and-forget support prefetch (consumer blocks only) --
    if (is_p2) {
        const float4* Sg = reinterpret_cast<const float4*>(support + (size_t)bn * KK * DD);
        unsigned saddr;
        asm("{ .reg .u64 t; cvta.to.shared.u64 t, %1; cvt.u32.u64 %0, t; }"
            : "=r"(saddr) : "l"(&s_sup[0]));
        #pragma unroll
        for (int i = 0; i < 15; i++) {               // KK*D4 = 1920 = 15*128
            unsigned dst = saddr + (unsigned)(i * TPB + tid) * 16u;
            const float4* src = Sg + i * TPB + tid;
            asm volatile("cp.async.ca.shared.global [%0], [%1], 16;"
                         :: "r"(dst), "l"(src));
        }
        asm volatile("cp.async.commit_group;");
    }

    // ================= Phase 1: partial query reduction (R13-identical) =====
    {
        const int b = bn >> 5;               // bn / CH
        const int c = bn & 31;               // bn % CH
        const float4* qb = reinterpret_cast<const float4*>(query)
                         + (size_t)b * QTOT * D4 + (size_t)c * QC * D4;

        float4 acc0 = make_float4(0.f, 0.f, 0.f, 0.f);
        float4 acc1 = make_float4(0.f, 0.f, 0.f, 0.f);
        float4 acc2 = make_float4(0.f, 0.f, 0.f, 0.f);
        float sq = 0.0f;

        #pragma unroll
        for (int q = 0; q < QC; q++) {
            const float4* row = qb + (size_t)q * D4;
            float4 v0 = row[tid];
            float4 v1 = row[tid + 128];
            float4 v2 = row[tid + 256];
            acc0.x += v0.x; acc0.y += v0.y; acc0.z += v0.z; acc0.w += v0.w;
            acc1.x += v1.x; acc1.y += v1.y; acc1.z += v1.z; acc1.w += v1.w;
            acc2.x += v2.x; acc2.y += v2.y; acc2.z += v2.z; acc2.w += v2.w;
            sq += v0.x*v0.x + v0.y*v0.y + v0.z*v0.z + v0.w*v0.w;
            sq += v1.x*v1.x + v1.y*v1.y + v1.z*v1.z + v1.w*v1.w;
            sq += v2.x*v2.x + v2.y*v2.y + v2.z*v2.z + v2.w*v2.w;
        }

        float4* dst = reinterpret_cast<float4*>(&g_part[b][c][0]);
        dst[tid]       = acc0;
        dst[tid + 128] = acc1;
        dst[tid + 256] = acc2;

        #pragma unroll
        for (int off = 16; off > 0; off >>= 1)
            sq += __shfl_down_sync(0xFFFFFFFFu, sq, off);
        if (lane == 0) swsq[warp] = sq;
        __syncthreads();
        if (tid == 0)
            g_sq[b][c] = swsq[0] + swsq[1] + swsq[2] + swsq[3];
    }

    // ===== Barrier: everyone arrives; ONLY consumers spin ===================
    __threadfence();              // publish partial stores
    __syncthreads();
    if (tid == 0) atomicAdd(&g_bar, 1u);

    if (is_p2) {
        if (tid == 0) {
            while (*((volatile unsigned*)&g_bar) < GRID) { }
        }
        __syncthreads();
        __threadfence();          // acquire

        // ============= Phase 2: per-(b,n) weights + aggregation =============
        const int b = bn / NN;
        const float invQ = 1.0f / (float)QTOT;

        // q-bar for this thread's 3 float4 columns (partials L2-hot)
        float4 qb0 = make_float4(0.f,0.f,0.f,0.f);
        float4 qb1 = make_float4(0.f,0.f,0.f,0.f);
        float4 qb2 = make_float4(0.f,0.f,0.f,0.f);
        const float4* pbase = reinterpret_cast<const float4*>(&g_part[b][0][0]);
        #pragma unroll 8
        for (int c = 0; c < CH; c++) {
            const float4* p = pbase + (size_t)c * D4;
            float4 v0 = p[tid], v1 = p[tid + 128], v2 = p[tid + 256];
            qb0.x += v0.x; qb0.y += v0.y; qb0.z += v0.z; qb0.w += v0.w;
            qb1.x += v1.x; qb1.y += v1.y; qb1.z += v1.z; qb1.w += v1.w;
            qb2.x += v2.x; qb2.y += v2.y; qb2.z += v2.z; qb2.w += v2.w;
        }

        // support tile now resident in smem
        asm volatile("cp.async.wait_group 0;");
        __syncthreads();

        float4 s0[KK], s1[KK], s2[KK];
        float dot[KK], sn[KK];
        #pragma unroll
        for (int k = 0; k < KK; k++) {
            const float4* Sk = reinterpret_cast<const float4*>(&s_sup[k * DD]);
            s0[k] = Sk[tid]; s1[k] = Sk[tid + 128]; s2[k] = Sk[tid + 256];
            dot[k] = s0[k].x*qb0.x + s0[k].y*qb0.y + s0[k].z*qb0.z + s0[k].w*qb0.w
                   + s1[k].x*qb1.x + s1[k].y*qb1.y + s1[k].z*qb1.z + s1[k].w*qb1.w
                   + s2[k].x*qb2.x + s2[k].y*qb2.y + s2[k].z*qb2.z + s2[k].w*qb2.w;
            sn[k]  = s0[k].x*s0[k].x + s0[k].y*s0[k].y + s0[k].z*s0[k].z + s0[k].w*s0[k].w
                   + s1[k].x*s1[k].x + s1[k].y*s1[k].y + s1[k].z*s1[k].z + s1[k].w*s1[k].w
                   + s2[k].x*s2[k].x + s2[k].y*s2[k].y + s2[k].z*s2[k].z + s2[k].w*s2[k].w;
        }

        #pragma unroll
        for (int k = 0; k < KK; k++) {
            float dv = dot[k], nv = sn[k];
            #pragma unroll
            for (int off = 16; off > 0; off >>= 1) {
                dv += __shfl_down_sync(0xFFFFFFFFu, dv, off);
                nv += __shfl_down_sync(0xFFFFFFFFu, nv, off);
            }
            if (lane == 0) { sred[k][warp] = dv; sred[KK + k][warp] = nv; }
        }
        __syncthreads();

        if (tid == 0) {
            float qn = 0.f;
            #pragma unroll
            for (int c = 0; c < CH; c++) qn += g_sq[b][c];
            qn *= invQ;                             // mean_q ||q||^2

            float t[KK], mx = -1e30f;
            #pragma unroll
            for (int k = 0; k < KK; k++) {
                float ds = sred[k][0] + sred[k][1] + sred[k][2] + sred[k][3];
                float ns = sred[KK+k][0] + sred[KK+k][1] + sred[KK+k][2] + sred[KK+k][3];
                float m = -(ns - 2.0f * ds * invQ + qn);   // mean_q dist_sq
                t[k] = tanhf(m);
                mx = fmaxf(mx, t[k]);
            }
            float es = 0.f;
            #pragma unroll
            for (int k = 0; k < KK; k++) { t[k] = __expf(t[k] - mx); es += t[k]; }
            float inv = 1.0f / es;
            #pragma unroll
            for (int k = 0; k < KK; k++) {
                float wk = t[k] * inv;
                sw[k] = wk;
                out_qgw[bn * KK + k] = wk;
            }
        }
        __syncthreads();

        float w0 = sw[0], w1 = sw[1], w2 = sw[2], w3 = sw[3], w4 = sw[4];
        float4* Oa = reinterpret_cast<float4*>(out_agg + (size_t)bn * DD);
        float4 a;
        a.x = s0[0].x*w0 + s0[1].x*w1 + s0[2].x*w2 + s0[3].x*w3 + s0[4].x*w4;
        a.y = s0[0].y*w0 + s0[1].y*w1 + s0[2].y*w2 + s0[3].y*w3 + s0[4].y*w4;
        a.z = s0[0].z*w0 + s0[1].z*w1 + s0[2].z*w2 + s0[3].z*w3 + s0[4].z*w4;
        a.w = s0[0].w*w0 + s0[1].w*w1 + s0[2].w*w2 + s0[3].w*w3 + s0[4].w*w4;
        Oa[tid] = a;
        a.x = s1[0].x*w0 + s1[1].x*w1 + s1[2].x*w2 + s1[3].x*w3 + s1[4].x*w4;
        a.y = s1[0].y*w0 + s1[1].y*w1 + s1[2].y*w2 + s1[3].y*w3 + s1[4].y*w4;
        a.z = s1[0].z*w0 + s1[1].z*w1 + s1[2].z*w2 + s1[3].z*w3 + s1[4].z*w4;
        a.w = s1[0].w*w0 + s1[1].w*w1 + s1[2].w*w2 + s1[3].w*w3 + s1[4].w*w4;
        Oa[tid + 128] = a;
        a.x = s2[0].x*w0 + s2[1].x*w1 + s2[2].x*w2 + s2[3].x*w3 + s2[4].x*w4;
        a.y = s2[0].y*w0 + s2[1].y*w1 + s2[2].y*w2 + s2[3].y*w3 + s2[4].y*w4;
        a.z = s2[0].z*w0 + s2[1].z*w1 + s2[2].z*w2 + s2[3].z*w3 + s2[4].z*w4;
        a.w = s2[0].w*w0 + s2[1].w*w1 + s2[2].w*w2 + s2[3].w*w3 + s2[4].w*w4;
        Oa[tid + 256] = a;
    } else {
        // non-consumers: drain the (unused) cp.async group state and leave
        __syncthreads();
    }

    // ---- Counter reset by the last block to finish --------------------------
    if (tid == 0) {
        unsigned old = atomicAdd(&g_done, 1u);
        if (old == GRID - 1) {          // everyone arrived at g_bar before g_done
            atomicExch(&g_bar, 0u);
            atomicExch(&g_done, 0u);
        }
    }
}

extern "C" void kernel_launch(void* const* d_in, const int* in_sizes, int n_in,
                              void* d_out, int out_size) {
    const float* support = (const float*)d_in[0];
    const float* query   = (const float*)d_in[1];
    float* out = (float*)d_out;

    float* out_agg = out;                          // (B,N,D)
    float* out_qgw = out + (size_t)BB * NN * DD;   // (B,N,K,1)

    fused_kernel<<<GRID, TPB>>>(support, query, out_agg, out_qgw);
}